// round 10
// baseline (speedup 1.0000x reference)
#include <cuda_runtime.h>
#include <cuda_fp16.h>
#include <cstdint>
#include <math.h>

#define BB 2
#define NN 2048
#define CC 1024
#define HH 16
#define DD 64
#define E3 3072
#define MM (BB*NN)   // 4096
#define BH (BB*HH)   // 32

// ---------------- scratch (no allocations allowed) ----------------
// Q/K/V and attention output stored as fp16 hi/lo pairs.
__device__ __half g_qh[BH * NN * DD], g_ql[BH * NN * DD];
__device__ __half g_kh[BH * NN * DD], g_kl[BH * NN * DD];
__device__ __half g_vh[BH * NN * DD], g_vl[BH * NN * DD];
__device__ __half g_aoh[MM * CC],    g_aol[MM * CC];
__device__ __half g_wqh[E3 * CC],    g_wql[E3 * CC];
__device__ __half g_woh[CC * CC],    g_wol[CC * CC];

__device__ __forceinline__ uint32_t smem_u32(const void* p) {
    uint32_t a;
    asm("{ .reg .u64 t; cvta.to.shared.u64 t, %1; cvt.u32.u64 %0, t; }" : "=r"(a) : "l"(p));
    return a;
}
__device__ __forceinline__ void mma16816(float* c, const uint32_t* a, const uint32_t* b) {
    asm volatile("mma.sync.aligned.m16n8k16.row.col.f32.f16.f16.f32 "
        "{%0,%1,%2,%3}, {%4,%5,%6,%7}, {%8,%9}, {%0,%1,%2,%3};"
        : "+f"(c[0]), "+f"(c[1]), "+f"(c[2]), "+f"(c[3])
        : "r"(a[0]), "r"(a[1]), "r"(a[2]), "r"(a[3]), "r"(b[0]), "r"(b[1]));
}
__device__ __forceinline__ void ldsm_x4(uint32_t* r, uint32_t addr) {
    asm volatile("ldmatrix.sync.aligned.m8n8.x4.shared.b16 {%0,%1,%2,%3}, [%4];"
        : "=r"(r[0]), "=r"(r[1]), "=r"(r[2]), "=r"(r[3]) : "r"(addr));
}
__device__ __forceinline__ void ldsm_x2(uint32_t* r, uint32_t addr) {
    asm volatile("ldmatrix.sync.aligned.m8n8.x2.shared.b16 {%0,%1}, [%2];"
        : "=r"(r[0]), "=r"(r[1]) : "r"(addr));
}
__device__ __forceinline__ void ldsm_x2t(uint32_t* r, uint32_t addr) {
    asm volatile("ldmatrix.sync.aligned.m8n8.x2.trans.shared.b16 {%0,%1}, [%2];"
        : "=r"(r[0]), "=r"(r[1]) : "r"(addr));
}
__device__ __forceinline__ uint32_t packh2(__half a, __half b) {
    __half2 t = __halves2half2(a, b);
    return *reinterpret_cast<uint32_t*>(&t);
}
__device__ __forceinline__ void cvt_split(float4 v, uint2& h, uint2& l) {
    __half h0 = __float2half_rn(v.x), h1 = __float2half_rn(v.y);
    __half h2 = __float2half_rn(v.z), h3 = __float2half_rn(v.w);
    h.x = packh2(h0, h1); h.y = packh2(h2, h3);
    l.x = packh2(__float2half_rn(v.x - __half2float(h0)),
                 __float2half_rn(v.y - __half2float(h1)));
    l.y = packh2(__float2half_rn(v.z - __half2float(h2)),
                 __float2half_rn(v.w - __half2float(h3)));
}
__device__ __forceinline__ void split2(float x, float y, __half2& h, __half2& l) {
    __half hx = __float2half_rn(x), hy = __float2half_rn(y);
    h = __halves2half2(hx, hy);
    l = __halves2half2(__float2half_rn(x - __half2float(hx)),
                       __float2half_rn(y - __half2float(hy)));
}
__device__ __forceinline__ void cp16(uint32_t saddr, const void* gaddr) {
    asm volatile("cp.async.cg.shared.global [%0], [%1], 16;" :: "r"(saddr), "l"(gaddr));
}
#define CP_COMMIT() asm volatile("cp.async.commit_group;" ::: "memory")
#define CP_WAIT0()  asm volatile("cp.async.wait_group 0;" ::: "memory")
#define CP_WAIT1()  asm volatile("cp.async.wait_group 1;" ::: "memory")

// ---------------- weight pre-split ----------------
__global__ __launch_bounds__(256) void wsplit_kernel(const float* __restrict__ src,
                                                     int which, int n4)
{
    __half* hi = (which == 0) ? g_wqh : g_woh;
    __half* lo = (which == 0) ? g_wql : g_wol;
    int i = blockIdx.x * blockDim.x + threadIdx.x;
    if (i >= n4) return;
    float4 a = ((const float4*)src)[i];
    uint2 h, l;
    cvt_split(a, h, l);
    *(uint2*)(hi + (size_t)i * 4) = h;
    *(uint2*)(lo + (size_t)i * 4) = l;
}

// ---------------- mma.sync fp16-split GEMM ----------------
// MODE 0: A = x fp32 (inline split), B = W_qkv pre-split; epilogue -> q/k/v hi/lo (q pre-scaled 1/8).
// MODE 1: A = g_ao hi/lo (cp.async), B = W_out pre-split; epilogue -> out fp32 + bias.
// smem stage (halves): Ah @0, Al @5120, Bh @10240, Bl @15360; stage stride 20480.
#define GSMEM 81920
template<int MODE>
__global__ __launch_bounds__(512) void tc_gemm(const float* __restrict__ Ain,
                                               const float* __restrict__ bias,
                                               float* __restrict__ outp)
{
    extern __shared__ __half sm[];
    const int tid  = threadIdx.x;
    const int lane = tid & 31;
    const int wid  = tid >> 5;
    const int wm   = wid >> 2;
    const int wn   = wid & 3;
    const int m0 = blockIdx.y * 128;
    const int n0 = blockIdx.x * 128;

    const __half* pBh = (MODE == 0) ? g_wqh : g_woh;
    const __half* pBl = (MODE == 0) ? g_wql : g_wol;

    const uint32_t sbase = smem_u32(sm);
    const uint32_t a_row = wm * 32 + (lane & 15);
    const uint32_t a_kg  = (lane >> 4) << 3;
    const uint32_t b_kg  = ((lane >> 3) & 1) << 3;

    const int brow = tid >> 2;
    const int bkgc = (tid & 3) * 8;
    const __half* gBh = pBh + (size_t)(n0 + brow) * CC + bkgc;
    const __half* gBl = pBl + (size_t)(n0 + brow) * CC + bkgc;
    const __half* gAh = g_aoh + (size_t)(m0 + brow) * CC + bkgc;   // MODE 1 only
    const __half* gAl = g_aol + (size_t)(m0 + brow) * CC + bkgc;
    const uint32_t coff = (uint32_t)(brow * 40 + bkgc) * 2;

    float acc[2][4][4];
#pragma unroll
    for (int i = 0; i < 2; i++)
#pragma unroll
        for (int j = 0; j < 4; j++)
#pragma unroll
            for (int c = 0; c < 4; c++) acc[i][j][c] = 0.0f;

    float4 ra[2];
    if (MODE == 0) {
#pragma unroll
        for (int i = 0; i < 2; i++) {
            int slot = tid + i * 512;
            int row = slot >> 3, c4 = (slot & 7) * 4;
            ra[i] = *(const float4*)&Ain[(size_t)(m0 + row) * CC + c4];
        }
    }

    auto store_A = [&](int st) {
#pragma unroll
        for (int i = 0; i < 2; i++) {
            int slot = tid + i * 512;
            int row = slot >> 3, c = (slot & 7) * 4;
            uint2 h, l;
            cvt_split(ra[i], h, l);
            *(uint2*)&sm[st * 20480 +        row * 40 + c] = h;
            *(uint2*)&sm[st * 20480 + 5120 + row * 40 + c] = l;
        }
    };
    auto issue_tiles = [&](int st, int k0) {
        uint32_t base = sbase + st * 40960;
        cp16(base + 20480 + coff, gBh + k0);
        cp16(base + 30720 + coff, gBl + k0);
        if (MODE == 1) {
            cp16(base +         coff, gAh + k0);
            cp16(base + 10240 + coff, gAl + k0);
        }
    };

    issue_tiles(0, 0);
    CP_COMMIT();
    if (MODE == 0) store_A(0);
    CP_WAIT0();
    __syncthreads();

    for (int k0 = 0; k0 < CC; k0 += 32) {
        const int st   = (k0 >> 5) & 1;
        const bool nxt = (k0 + 32 < CC);

        if (nxt) {
            issue_tiles(st ^ 1, k0 + 32);
            CP_COMMIT();
            if (MODE == 0) {
#pragma unroll
                for (int i = 0; i < 2; i++) {
                    int slot = tid + i * 512;
                    int row = slot >> 3, c4 = (slot & 7) * 4;
                    ra[i] = *(const float4*)&Ain[(size_t)(m0 + row) * CC + k0 + 32 + c4];
                }
            }
        }

        const uint32_t base = sbase + st * 40960;
#pragma unroll
        for (int ks = 0; ks < 2; ks++) {
            const uint32_t kcol = ks * 16;
            uint32_t ah[2][4], al[2][4];
#pragma unroll
            for (int mt = 0; mt < 2; mt++) {
                uint32_t off = ((a_row + mt * 16) * 40 + kcol + a_kg) * 2;
                ldsm_x4(ah[mt], base + off);
                ldsm_x4(al[mt], base + 10240 + off);
            }
#pragma unroll
            for (int nt = 0; nt < 4; nt++) {
                uint32_t boff = ((wn * 32 + nt * 8 + (lane & 7)) * 40 + kcol + b_kg) * 2;
                uint32_t bhr[2], blr[2];
                ldsm_x2(bhr, base + 20480 + boff);
                ldsm_x2(blr, base + 30720 + boff);
#pragma unroll
                for (int mt = 0; mt < 2; mt++) {
                    mma16816(acc[mt][nt], ah[mt], bhr);
                    mma16816(acc[mt][nt], ah[mt], blr);
                    mma16816(acc[mt][nt], al[mt], bhr);
                }
            }
            if (MODE == 0 && ks == 0 && nxt) store_A(st ^ 1);
        }

        if (nxt) CP_WAIT0();
        __syncthreads();
    }

    // Epilogue
#pragma unroll
    for (int mt = 0; mt < 2; mt++) {
#pragma unroll
        for (int nt = 0; nt < 4; nt++) {
            const float* c = acc[mt][nt];
            const int col = n0 + wn * 32 + nt * 8 + (lane & 3) * 2;
#pragma unroll
            for (int hr = 0; hr < 2; hr++) {
                const int row = m0 + wm * 32 + mt * 16 + (lane >> 2) + hr * 8;
                float vx = c[hr * 2 + 0], vy = c[hr * 2 + 1];
                if (MODE == 0) {
                    const int part = col >> 10, rr = col & 1023;
                    const int h = rr >> 6, d = rr & 63;
                    __half* dh = (part == 0) ? g_qh : (part == 1) ? g_kh : g_vh;
                    __half* dl = (part == 0) ? g_ql : (part == 1) ? g_kl : g_vl;
                    if (part == 0) { vx *= 0.125f; vy *= 0.125f; }
                    const int b = row >> 11, n = row & 2047;
                    const size_t addr = ((size_t)(b * HH + h) * NN + n) * DD + d;
                    __half2 hh, ll;
                    split2(vx, vy, hh, ll);
                    *(__half2*)&dh[addr] = hh;
                    *(__half2*)&dl[addr] = ll;
                } else {
                    vx += bias[col];
                    vy += bias[col + 1];
                    *(float2*)&outp[(size_t)row * CC + col] = make_float2(vx, vy);
                }
            }
        }
    }
}

// ---------------- MMA flash attention, cp.async double-buffered K/V ----------------
// Dynamic smem 73728 B = 2 stages x (Kh|Kl|Vh|Vl)[64][72].
// Q staging overlays stage 0 before the main loop.
// Stage byte offsets within stage: Kh 0, Kl 9216, Vh 18432, Vl 27648.
#define ATT_SMEM 73728
__global__ __launch_bounds__(256) void attn_mma_kernel()
{
    extern __shared__ __half smh[];
    const int bh   = blockIdx.y;
    const int q0   = blockIdx.x * 128;
    const int tid  = threadIdx.x;
    const int lane = tid & 31;
    const int warp = tid >> 5;

    const uint32_t sbase = smem_u32(smh);
    const size_t hb = (size_t)bh * NN * DD;
    const __half* kvsrc[4] = { g_kh + hb, g_kl + hb, g_vh + hb, g_vl + hb };

    // ---- prologue: Q (stage-0 region) + KV tile 0 (stage-1 region) via cp.async ----
#pragma unroll
    for (int i = 0; i < 8; i++) {
        const int mat = i >> 2;                 // 0: Qh, 1: Ql
        const int s = tid + (i & 3) * 256;      // 1024 chunks per matrix
        const int row = s >> 3, c = (s & 7) * 8;
        const __half* src = ((mat == 0) ? g_qh : g_ql) + hb + (size_t)(q0 + row) * DD + c;
        cp16(sbase + mat * 18432 + (row * 72 + c) * 2, src);
    }
    CP_COMMIT();
#pragma unroll
    for (int i = 0; i < 8; i++) {
        const int mat = i >> 1;                 // Kh,Kl,Vh,Vl
        const int s = tid + (i & 1) * 256;      // 512 chunks per matrix
        const int row = s >> 3, c = (s & 7) * 8;
        cp16(sbase + 36864 + mat * 9216 + (row * 72 + c) * 2,
             kvsrc[mat] + (size_t)row * DD + c);
    }
    CP_COMMIT();
    CP_WAIT1();          // Q arrived (tile 0 may still be in flight)
    __syncthreads();

    // ---- Q fragments ----
    uint32_t qh[4][4], ql[4][4];
    {
        const uint32_t arow = warp * 16 + (lane & 15);
        const uint32_t akg  = ((lane >> 4) & 1) * 8;
#pragma unroll
        for (int ks = 0; ks < 4; ks++) {
            uint32_t off = (arow * 72 + ks * 16 + akg) * 2;
            ldsm_x4(qh[ks], sbase + off);
            ldsm_x4(ql[ks], sbase + 18432 + off);
        }
    }
    __syncthreads();     // Q region free; tile 1 may overwrite it

    float O[8][4];
#pragma unroll
    for (int n = 0; n < 8; n++)
#pragma unroll
        for (int c = 0; c < 4; c++) O[n][c] = 0.0f;
    float m0r = -1e30f, m1r = -1e30f;
    float l0 = 0.0f, l1 = 0.0f;

    const uint32_t bkey = (lane & 7);
    const uint32_t bkg  = ((lane >> 3) & 1) * 8;
    const uint32_t vrow = (lane & 15);

    for (int t = 0; t < 32; t++) {
        // tile t lives in stage (t even -> 1, t odd -> 0)
        const uint32_t base = sbase + ((t & 1) ? 0u : 36864u);

        if (t + 1 < 32) {
            const uint32_t nbase = sbase + ((t & 1) ? 36864u : 0u);
            const int j0 = (t + 1) * 64;
#pragma unroll
            for (int i = 0; i < 8; i++) {
                const int mat = i >> 1;
                const int s = tid + (i & 1) * 256;
                const int row = s >> 3, c = (s & 7) * 8;
                cp16(nbase + mat * 9216 + (row * 72 + c) * 2,
                     kvsrc[mat] + (size_t)(j0 + row) * DD + c);
            }
            CP_COMMIT();
            CP_WAIT1();
        } else {
            CP_WAIT0();
        }
        __syncthreads();

        // ---- scores ----
        float s[8][4];
#pragma unroll
        for (int n = 0; n < 8; n++)
#pragma unroll
            for (int c = 0; c < 4; c++) s[n][c] = 0.0f;

#pragma unroll
        for (int ks = 0; ks < 4; ks++) {
#pragma unroll
            for (int nt = 0; nt < 8; nt++) {
                uint32_t boff = ((nt * 8 + bkey) * 72 + ks * 16 + bkg) * 2;
                uint32_t kbh[2], kbl[2];
                ldsm_x2(kbh, base + boff);
                ldsm_x2(kbl, base + 9216 + boff);
                mma16816(s[nt], qh[ks], kbh);
                mma16816(s[nt], qh[ks], kbl);
                mma16816(s[nt], ql[ks], kbh);
            }
        }

        // ---- online softmax ----
        float mloc0 = -1e30f, mloc1 = -1e30f;
#pragma unroll
        for (int nt = 0; nt < 8; nt++) {
            mloc0 = fmaxf(mloc0, fmaxf(s[nt][0], s[nt][1]));
            mloc1 = fmaxf(mloc1, fmaxf(s[nt][2], s[nt][3]));
        }
        mloc0 = fmaxf(mloc0, __shfl_xor_sync(0xffffffffu, mloc0, 1));
        mloc0 = fmaxf(mloc0, __shfl_xor_sync(0xffffffffu, mloc0, 2));
        mloc1 = fmaxf(mloc1, __shfl_xor_sync(0xffffffffu, mloc1, 1));
        mloc1 = fmaxf(mloc1, __shfl_xor_sync(0xffffffffu, mloc1, 2));

        float mn0 = fmaxf(m0r, mloc0), mn1 = fmaxf(m1r, mloc1);
        float cr0 = __expf(m0r - mn0), cr1 = __expf(m1r - mn1);
        m0r = mn0; m1r = mn1;
        l0 *= cr0; l1 *= cr1;
#pragma unroll
        for (int n = 0; n < 8; n++) {
            O[n][0] *= cr0; O[n][1] *= cr0;
            O[n][2] *= cr1; O[n][3] *= cr1;
        }

        float ls0 = 0.0f, ls1 = 0.0f;
        uint32_t aPh[4][4], aPl[4][4];
#pragma unroll
        for (int nt = 0; nt < 8; nt++) {
            float p0 = __expf(s[nt][0] - m0r);
            float p1 = __expf(s[nt][1] - m0r);
            float p2 = __expf(s[nt][2] - m1r);
            float p3 = __expf(s[nt][3] - m1r);
            ls0 += p0 + p1; ls1 += p2 + p3;
            __half h0 = __float2half_rn(p0), h1 = __float2half_rn(p1);
            __half h2 = __float2half_rn(p2), h3 = __float2half_rn(p3);
            const int kt = nt >> 1, hi2 = (nt & 1) * 2;
            aPh[kt][hi2 + 0] = packh2(h0, h1);
            aPh[kt][hi2 + 1] = packh2(h2, h3);
            aPl[kt][hi2 + 0] = packh2(__float2half_rn(p0 - __half2float(h0)),
                                      __float2half_rn(p1 - __half2float(h1)));
            aPl[kt][hi2 + 1] = packh2(__float2half_rn(p2 - __half2float(h2)),
                                      __float2half_rn(p3 - __half2float(h3)));
        }
        ls0 += __shfl_xor_sync(0xffffffffu, ls0, 1);
        ls0 += __shfl_xor_sync(0xffffffffu, ls0, 2);
        ls1 += __shfl_xor_sync(0xffffffffu, ls1, 1);
        ls1 += __shfl_xor_sync(0xffffffffu, ls1, 2);
        l0 += ls0; l1 += ls1;

        // ---- O += P . V ----
#pragma unroll
        for (int kt = 0; kt < 4; kt++) {
#pragma unroll
            for (int nd = 0; nd < 8; nd++) {
                uint32_t voff = ((kt * 16 + vrow) * 72 + nd * 8) * 2;
                uint32_t vbh[2], vbl[2];
                ldsm_x2t(vbh, base + 18432 + voff);
                ldsm_x2t(vbl, base + 27648 + voff);
                mma16816(O[nd], aPh[kt], vbh);
                mma16816(O[nd], aPh[kt], vbl);
                mma16816(O[nd], aPl[kt], vbh);
            }
        }
        __syncthreads();
    }

    // ---- epilogue: write hi/lo attention output ----
    const float inv0 = 1.0f / l0, inv1 = 1.0f / l1;
    const int b = bh >> 4, h = bh & 15;
    const int row0 = q0 + warp * 16 + (lane >> 2);
    const int row1 = row0 + 8;
#pragma unroll
    for (int nd = 0; nd < 8; nd++) {
        const int d = nd * 8 + (lane & 3) * 2;
        const size_t a0 = ((size_t)(b * NN + row0)) * CC + h * DD + d;
        const size_t a1 = ((size_t)(b * NN + row1)) * CC + h * DD + d;
        __half2 hh, ll;
        split2(O[nd][0] * inv0, O[nd][1] * inv0, hh, ll);
        *(__half2*)&g_aoh[a0] = hh;
        *(__half2*)&g_aol[a0] = ll;
        split2(O[nd][2] * inv1, O[nd][3] * inv1, hh, ll);
        *(__half2*)&g_aoh[a1] = hh;
        *(__half2*)&g_aol[a1] = ll;
    }
}

// ---------------------------------------------------------------------------
extern "C" void kernel_launch(void* const* d_in, const int* in_sizes, int n_in,
                              void* d_out, int out_size)
{
    const float* x     = (const float*)d_in[0];
    const float* W_qkv = (const float*)d_in[1];
    const float* W_out = (const float*)d_in[2];
    const float* b_out = (const float*)d_in[3];
    float* out = (float*)d_out;
    (void)in_sizes; (void)n_in; (void)out_size;

    cudaFuncSetAttribute(tc_gemm<0>, cudaFuncAttributeMaxDynamicSharedMemorySize, GSMEM);
    cudaFuncSetAttribute(tc_gemm<1>, cudaFuncAttributeMaxDynamicSharedMemorySize, GSMEM);
    cudaFuncSetAttribute(attn_mma_kernel, cudaFuncAttributeMaxDynamicSharedMemorySize, ATT_SMEM);

    wsplit_kernel<<<(E3 * CC / 4 + 255) / 256, 256>>>(W_qkv, 0, E3 * CC / 4);
    wsplit_kernel<<<(CC * CC / 4 + 255) / 256, 256>>>(W_out, 1, CC * CC / 4);

    {
        dim3 grid(E3 / 128, MM / 128);   // (24, 32)
        tc_gemm<0><<<grid, 512, GSMEM>>>(x, nullptr, nullptr);
    }
    {
        dim3 grid(NN / 128, BH);
        attn_mma_kernel<<<grid, 256, ATT_SMEM>>>();
    }
    {
        dim3 grid(CC / 128, MM / 128);   // (8, 32)
        tc_gemm<1><<<grid, 512, GSMEM>>>(nullptr, b_out, out);
    }
}

// round 12
// speedup vs baseline: 1.2494x; 1.2494x over previous
#include <cuda_runtime.h>
#include <cuda_fp16.h>
#include <cstdint>
#include <math.h>

#define BB 2
#define NN 2048
#define CC 1024
#define HH 16
#define DD 64
#define E3 3072
#define MM (BB*NN)   // 4096
#define BH (BB*HH)   // 32

// Q scale: 1/sqrt(64) * log2(e)  (scores computed in log2 domain for ex2.approx)
#define QSCALE 0.1803368801111204f

// ---------------- scratch (no allocations allowed) ----------------
__device__ __half g_qh[BH * NN * DD];                      // Q: fp16 hi only (pre-scaled)
__device__ __half g_kh[BH * NN * DD], g_kl[BH * NN * DD];
__device__ __half g_vh[BH * NN * DD], g_vl[BH * NN * DD];
__device__ __half g_aoh[MM * CC],    g_aol[MM * CC];
__device__ __half g_wqh[E3 * CC],    g_wql[E3 * CC];
__device__ __half g_woh[CC * CC],    g_wol[CC * CC];

__device__ __forceinline__ float ex2f(float x) {
    float r;
    asm("ex2.approx.f32 %0, %1;" : "=f"(r) : "f"(x));
    return r;
}
__device__ __forceinline__ uint32_t smem_u32(const void* p) {
    uint32_t a;
    asm("{ .reg .u64 t; cvta.to.shared.u64 t, %1; cvt.u32.u64 %0, t; }" : "=r"(a) : "l"(p));
    return a;
}
__device__ __forceinline__ void mma16816(float* c, const uint32_t* a, const uint32_t* b) {
    asm volatile("mma.sync.aligned.m16n8k16.row.col.f32.f16.f16.f32 "
        "{%0,%1,%2,%3}, {%4,%5,%6,%7}, {%8,%9}, {%0,%1,%2,%3};"
        : "+f"(c[0]), "+f"(c[1]), "+f"(c[2]), "+f"(c[3])
        : "r"(a[0]), "r"(a[1]), "r"(a[2]), "r"(a[3]), "r"(b[0]), "r"(b[1]));
}
__device__ __forceinline__ void ldsm_x4(uint32_t* r, uint32_t addr) {
    asm volatile("ldmatrix.sync.aligned.m8n8.x4.shared.b16 {%0,%1,%2,%3}, [%4];"
        : "=r"(r[0]), "=r"(r[1]), "=r"(r[2]), "=r"(r[3]) : "r"(addr));
}
__device__ __forceinline__ void ldsm_x2(uint32_t* r, uint32_t addr) {
    asm volatile("ldmatrix.sync.aligned.m8n8.x2.shared.b16 {%0,%1}, [%2];"
        : "=r"(r[0]), "=r"(r[1]) : "r"(addr));
}
__device__ __forceinline__ void ldsm_x2t(uint32_t* r, uint32_t addr) {
    asm volatile("ldmatrix.sync.aligned.m8n8.x2.trans.shared.b16 {%0,%1}, [%2];"
        : "=r"(r[0]), "=r"(r[1]) : "r"(addr));
}
__device__ __forceinline__ uint32_t packh2(__half a, __half b) {
    __half2 t = __halves2half2(a, b);
    return *reinterpret_cast<uint32_t*>(&t);
}
__device__ __forceinline__ void cvt_split(float4 v, uint2& h, uint2& l) {
    __half h0 = __float2half_rn(v.x), h1 = __float2half_rn(v.y);
    __half h2 = __float2half_rn(v.z), h3 = __float2half_rn(v.w);
    h.x = packh2(h0, h1); h.y = packh2(h2, h3);
    l.x = packh2(__float2half_rn(v.x - __half2float(h0)),
                 __float2half_rn(v.y - __half2float(h1)));
    l.y = packh2(__float2half_rn(v.z - __half2float(h2)),
                 __float2half_rn(v.w - __half2float(h3)));
}
__device__ __forceinline__ void split2(float x, float y, __half2& h, __half2& l) {
    __half hx = __float2half_rn(x), hy = __float2half_rn(y);
    h = __halves2half2(hx, hy);
    l = __halves2half2(__float2half_rn(x - __half2float(hx)),
                       __float2half_rn(y - __half2float(hy)));
}
__device__ __forceinline__ void cp16(uint32_t saddr, const void* gaddr) {
    asm volatile("cp.async.cg.shared.global [%0], [%1], 16;" :: "r"(saddr), "l"(gaddr));
}
#define CP_COMMIT() asm volatile("cp.async.commit_group;" ::: "memory")
#define CP_WAIT0()  asm volatile("cp.async.wait_group 0;" ::: "memory")
#define CP_WAIT1()  asm volatile("cp.async.wait_group 1;" ::: "memory")

// ---------------- weight pre-split ----------------
__global__ __launch_bounds__(256) void wsplit_kernel(const float* __restrict__ src,
                                                     int which, int n4)
{
    __half* hi = (which == 0) ? g_wqh : g_woh;
    __half* lo = (which == 0) ? g_wql : g_wol;
    int i = blockIdx.x * blockDim.x + threadIdx.x;
    if (i >= n4) return;
    float4 a = ((const float4*)src)[i];
    uint2 h, l;
    cvt_split(a, h, l);
    *(uint2*)(hi + (size_t)i * 4) = h;
    *(uint2*)(lo + (size_t)i * 4) = l;
}

// ---------------- mma.sync fp16-split GEMM (3-term) ----------------
#define GSMEM 81920
template<int MODE>
__global__ __launch_bounds__(512) void tc_gemm(const float* __restrict__ Ain,
                                               const float* __restrict__ bias,
                                               float* __restrict__ outp)
{
    extern __shared__ __half sm[];
    const int tid  = threadIdx.x;
    const int lane = tid & 31;
    const int wid  = tid >> 5;
    const int wm   = wid >> 2;
    const int wn   = wid & 3;
    const int m0 = blockIdx.y * 128;
    const int n0 = blockIdx.x * 128;

    const __half* pBh = (MODE == 0) ? g_wqh : g_woh;
    const __half* pBl = (MODE == 0) ? g_wql : g_wol;

    const uint32_t sbase = smem_u32(sm);
    const uint32_t a_row = wm * 32 + (lane & 15);
    const uint32_t a_kg  = (lane >> 4) << 3;
    const uint32_t b_kg  = ((lane >> 3) & 1) << 3;

    const int brow = tid >> 2;
    const int bkgc = (tid & 3) * 8;
    const __half* gBh = pBh + (size_t)(n0 + brow) * CC + bkgc;
    const __half* gBl = pBl + (size_t)(n0 + brow) * CC + bkgc;
    const __half* gAh = g_aoh + (size_t)(m0 + brow) * CC + bkgc;
    const __half* gAl = g_aol + (size_t)(m0 + brow) * CC + bkgc;
    const uint32_t coff = (uint32_t)(brow * 40 + bkgc) * 2;

    float acc[2][4][4];
#pragma unroll
    for (int i = 0; i < 2; i++)
#pragma unroll
        for (int j = 0; j < 4; j++)
#pragma unroll
            for (int c = 0; c < 4; c++) acc[i][j][c] = 0.0f;

    float4 ra[2];
    if (MODE == 0) {
#pragma unroll
        for (int i = 0; i < 2; i++) {
            int slot = tid + i * 512;
            int row = slot >> 3, c4 = (slot & 7) * 4;
            ra[i] = *(const float4*)&Ain[(size_t)(m0 + row) * CC + c4];
        }
    }

    auto store_A = [&](int st) {
#pragma unroll
        for (int i = 0; i < 2; i++) {
            int slot = tid + i * 512;
            int row = slot >> 3, c = (slot & 7) * 4;
            uint2 h, l;
            cvt_split(ra[i], h, l);
            *(uint2*)&sm[st * 20480 +        row * 40 + c] = h;
            *(uint2*)&sm[st * 20480 + 5120 + row * 40 + c] = l;
        }
    };
    auto issue_tiles = [&](int st, int k0) {
        uint32_t base = sbase + st * 40960;
        cp16(base + 20480 + coff, gBh + k0);
        cp16(base + 30720 + coff, gBl + k0);
        if (MODE == 1) {
            cp16(base +         coff, gAh + k0);
            cp16(base + 10240 + coff, gAl + k0);
        }
    };

    issue_tiles(0, 0);
    CP_COMMIT();
    if (MODE == 0) store_A(0);
    CP_WAIT0();
    __syncthreads();

    for (int k0 = 0; k0 < CC; k0 += 32) {
        const int st   = (k0 >> 5) & 1;
        const bool nxt = (k0 + 32 < CC);

        if (nxt) {
            issue_tiles(st ^ 1, k0 + 32);
            CP_COMMIT();
            if (MODE == 0) {
#pragma unroll
                for (int i = 0; i < 2; i++) {
                    int slot = tid + i * 512;
                    int row = slot >> 3, c4 = (slot & 7) * 4;
                    ra[i] = *(const float4*)&Ain[(size_t)(m0 + row) * CC + k0 + 32 + c4];
                }
            }
        }

        const uint32_t base = sbase + st * 40960;
#pragma unroll
        for (int ks = 0; ks < 2; ks++) {
            const uint32_t kcol = ks * 16;
            uint32_t ah[2][4], al[2][4];
#pragma unroll
            for (int mt = 0; mt < 2; mt++) {
                uint32_t off = ((a_row + mt * 16) * 40 + kcol + a_kg) * 2;
                ldsm_x4(ah[mt], base + off);
                ldsm_x4(al[mt], base + 10240 + off);
            }
#pragma unroll
            for (int nt = 0; nt < 4; nt++) {
                uint32_t boff = ((wn * 32 + nt * 8 + (lane & 7)) * 40 + kcol + b_kg) * 2;
                uint32_t bhr[2], blr[2];
                ldsm_x2(bhr, base + 20480 + boff);
                ldsm_x2(blr, base + 30720 + boff);
#pragma unroll
                for (int mt = 0; mt < 2; mt++) {
                    mma16816(acc[mt][nt], ah[mt], bhr);
                    mma16816(acc[mt][nt], ah[mt], blr);
                    mma16816(acc[mt][nt], al[mt], bhr);
                }
            }
            if (MODE == 0 && ks == 0 && nxt) store_A(st ^ 1);
        }

        if (nxt) CP_WAIT0();
        __syncthreads();
    }

    // Epilogue
#pragma unroll
    for (int mt = 0; mt < 2; mt++) {
#pragma unroll
        for (int nt = 0; nt < 4; nt++) {
            const float* c = acc[mt][nt];
            const int col = n0 + wn * 32 + nt * 8 + (lane & 3) * 2;
#pragma unroll
            for (int hr = 0; hr < 2; hr++) {
                const int row = m0 + wm * 32 + mt * 16 + (lane >> 2) + hr * 8;
                float vx = c[hr * 2 + 0], vy = c[hr * 2 + 1];
                if (MODE == 0) {
                    const int part = col >> 10, rr = col & 1023;
                    const int h = rr >> 6, d = rr & 63;
                    const int b = row >> 11, n = row & 2047;
                    const size_t addr = ((size_t)(b * HH + h) * NN + n) * DD + d;
                    if (part == 0) {
                        vx *= QSCALE; vy *= QSCALE;
                        __half2 hh, ll;
                        split2(vx, vy, hh, ll);
                        *(__half2*)&g_qh[addr] = hh;          // hi only
                    } else {
                        __half* dh = (part == 1) ? g_kh : g_vh;
                        __half* dl = (part == 1) ? g_kl : g_vl;
                        __half2 hh, ll;
                        split2(vx, vy, hh, ll);
                        *(__half2*)&dh[addr] = hh;
                        *(__half2*)&dl[addr] = ll;
                    }
                } else {
                    vx += bias[col];
                    vy += bias[col + 1];
                    *(float2*)&outp[(size_t)row * CC + col] = make_float2(vx, vy);
                }
            }
        }
    }
}

// ---------------- MMA flash attention: 2-term QK, 2-term PV, 2 CTAs/SM --------
// Smem: 2 stages x (Kh|Kl|Vh|Vl)[64][72] = 73728 B. Qh staging overlays stage 0.
#define ATT_SMEM 73728
__global__ __launch_bounds__(256, 2) void attn_mma_kernel()
{
    extern __shared__ __half smh[];
    const int bh   = blockIdx.y;
    const int q0   = blockIdx.x * 128;
    const int tid  = threadIdx.x;
    const int lane = tid & 31;
    const int warp = tid >> 5;

    const uint32_t sbase = smem_u32(smh);
    const size_t hb = (size_t)bh * NN * DD;
    const __half* kvsrc[4] = { g_kh + hb, g_kl + hb, g_vh + hb, g_vl + hb };

    // ---- prologue: Qh (stage-0 region) + KV tile 0 (stage-1 region) ----
#pragma unroll
    for (int i = 0; i < 4; i++) {
        const int s = tid + i * 256;            // 1024 chunks (128 rows x 8)
        const int row = s >> 3, c = (s & 7) * 8;
        cp16(sbase + (row * 72 + c) * 2, g_qh + hb + (size_t)(q0 + row) * DD + c);
    }
    CP_COMMIT();
#pragma unroll
    for (int i = 0; i < 8; i++) {
        const int mat = i >> 1;
        const int s = tid + (i & 1) * 256;
        const int row = s >> 3, c = (s & 7) * 8;
        cp16(sbase + 36864 + mat * 9216 + (row * 72 + c) * 2,
             kvsrc[mat] + (size_t)row * DD + c);
    }
    CP_COMMIT();
    CP_WAIT1();
    __syncthreads();

    // ---- Q fragments (hi only) ----
    uint32_t qh[4][4];
    {
        const uint32_t arow = warp * 16 + (lane & 15);
        const uint32_t akg  = ((lane >> 4) & 1) * 8;
#pragma unroll
        for (int ks = 0; ks < 4; ks++)
            ldsm_x4(qh[ks], sbase + (arow * 72 + ks * 16 + akg) * 2);
    }
    __syncthreads();

    float O[8][4];
#pragma unroll
    for (int n = 0; n < 8; n++)
#pragma unroll
        for (int c = 0; c < 4; c++) O[n][c] = 0.0f;
    float m0r = -1e30f, m1r = -1e30f;
    float l0 = 0.0f, l1 = 0.0f;

    const uint32_t bkey = (lane & 7);
    const uint32_t bkg  = ((lane >> 3) & 1) * 8;
    const uint32_t vrow = (lane & 15);

    for (int t = 0; t < 32; t++) {
        const uint32_t base = sbase + ((t & 1) ? 0u : 36864u);

        if (t + 1 < 32) {
            const uint32_t nbase = sbase + ((t & 1) ? 36864u : 0u);
            const int j0 = (t + 1) * 64;
#pragma unroll
            for (int i = 0; i < 8; i++) {
                const int mat = i >> 1;
                const int s = tid + (i & 1) * 256;
                const int row = s >> 3, c = (s & 7) * 8;
                cp16(nbase + mat * 9216 + (row * 72 + c) * 2,
                     kvsrc[mat] + (size_t)(j0 + row) * DD + c);
            }
            CP_COMMIT();
            CP_WAIT1();
        } else {
            CP_WAIT0();
        }
        __syncthreads();

        // ---- scores: QhKh + QhKl (log2 domain) ----
        float s[8][4];
#pragma unroll
        for (int n = 0; n < 8; n++)
#pragma unroll
            for (int c = 0; c < 4; c++) s[n][c] = 0.0f;

#pragma unroll
        for (int ks = 0; ks < 4; ks++) {
#pragma unroll
            for (int nt = 0; nt < 8; nt++) {
                uint32_t boff = ((nt * 8 + bkey) * 72 + ks * 16 + bkg) * 2;
                uint32_t kbh[2], kbl[2];
                ldsm_x2(kbh, base + boff);
                ldsm_x2(kbl, base + 9216 + boff);
                mma16816(s[nt], qh[ks], kbh);
                mma16816(s[nt], qh[ks], kbl);
            }
        }

        // ---- online softmax (exp2) ----
        float mloc0 = -1e30f, mloc1 = -1e30f;
#pragma unroll
        for (int nt = 0; nt < 8; nt++) {
            mloc0 = fmaxf(mloc0, fmaxf(s[nt][0], s[nt][1]));
            mloc1 = fmaxf(mloc1, fmaxf(s[nt][2], s[nt][3]));
        }
        mloc0 = fmaxf(mloc0, __shfl_xor_sync(0xffffffffu, mloc0, 1));
        mloc0 = fmaxf(mloc0, __shfl_xor_sync(0xffffffffu, mloc0, 2));
        mloc1 = fmaxf(mloc1, __shfl_xor_sync(0xffffffffu, mloc1, 1));
        mloc1 = fmaxf(mloc1, __shfl_xor_sync(0xffffffffu, mloc1, 2));

        float mn0 = fmaxf(m0r, mloc0), mn1 = fmaxf(m1r, mloc1);
        float cr0 = ex2f(m0r - mn0), cr1 = ex2f(m1r - mn1);
        m0r = mn0; m1r = mn1;
        l0 *= cr0; l1 *= cr1;
#pragma unroll
        for (int n = 0; n < 8; n++) {
            O[n][0] *= cr0; O[n][1] *= cr0;
            O[n][2] *= cr1; O[n][3] *= cr1;
        }

        float ls0 = 0.0f, ls1 = 0.0f;
        uint32_t aPh[4][4];
#pragma unroll
        for (int nt = 0; nt < 8; nt++) {
            float p0 = ex2f(s[nt][0] - m0r);
            float p1 = ex2f(s[nt][1] - m0r);
            float p2 = ex2f(s[nt][2] - m1r);
            float p3 = ex2f(s[nt][3] - m1r);
            ls0 += p0 + p1; ls1 += p2 + p3;
            const int kt = nt >> 1, hi2 = (nt & 1) * 2;
            aPh[kt][hi2 + 0] = packh2(__float2half_rn(p0), __float2half_rn(p1));
            aPh[kt][hi2 + 1] = packh2(__float2half_rn(p2), __float2half_rn(p3));
        }
        ls0 += __shfl_xor_sync(0xffffffffu, ls0, 1);
        ls0 += __shfl_xor_sync(0xffffffffu, ls0, 2);
        ls1 += __shfl_xor_sync(0xffffffffu, ls1, 1);
        ls1 += __shfl_xor_sync(0xffffffffu, ls1, 2);
        l0 += ls0; l1 += ls1;

        // ---- O += PhVh + PhVl ----
#pragma unroll
        for (int kt = 0; kt < 4; kt++) {
#pragma unroll
            for (int nd = 0; nd < 8; nd++) {
                uint32_t voff = ((kt * 16 + vrow) * 72 + nd * 8) * 2;
                uint32_t vbh[2], vbl[2];
                ldsm_x2t(vbh, base + 18432 + voff);
                ldsm_x2t(vbl, base + 27648 + voff);
                mma16816(O[nd], aPh[kt], vbh);
                mma16816(O[nd], aPh[kt], vbl);
            }
        }
        __syncthreads();
    }

    // ---- epilogue: hi/lo attention output ----
    const float inv0 = 1.0f / l0, inv1 = 1.0f / l1;
    const int b = bh >> 4, h = bh & 15;
    const int row0 = q0 + warp * 16 + (lane >> 2);
    const int row1 = row0 + 8;
#pragma unroll
    for (int nd = 0; nd < 8; nd++) {
        const int d = nd * 8 + (lane & 3) * 2;
        const size_t a0 = ((size_t)(b * NN + row0)) * CC + h * DD + d;
        const size_t a1 = ((size_t)(b * NN + row1)) * CC + h * DD + d;
        __half2 hh, ll;
        split2(O[nd][0] * inv0, O[nd][1] * inv0, hh, ll);
        *(__half2*)&g_aoh[a0] = hh;
        *(__half2*)&g_aol[a0] = ll;
        split2(O[nd][2] * inv1, O[nd][3] * inv1, hh, ll);
        *(__half2*)&g_aoh[a1] = hh;
        *(__half2*)&g_aol[a1] = ll;
    }
}

// ---------------------------------------------------------------------------
extern "C" void kernel_launch(void* const* d_in, const int* in_sizes, int n_in,
                              void* d_out, int out_size)
{
    const float* x     = (const float*)d_in[0];
    const float* W_qkv = (const float*)d_in[1];
    const float* W_out = (const float*)d_in[2];
    const float* b_out = (const float*)d_in[3];
    float* out = (float*)d_out;
    (void)in_sizes; (void)n_in; (void)out_size;

    cudaFuncSetAttribute(tc_gemm<0>, cudaFuncAttributeMaxDynamicSharedMemorySize, GSMEM);
    cudaFuncSetAttribute(tc_gemm<1>, cudaFuncAttributeMaxDynamicSharedMemorySize, GSMEM);
    cudaFuncSetAttribute(attn_mma_kernel, cudaFuncAttributeMaxDynamicSharedMemorySize, ATT_SMEM);

    wsplit_kernel<<<(E3 * CC / 4 + 255) / 256, 256>>>(W_qkv, 0, E3 * CC / 4);
    wsplit_kernel<<<(CC * CC / 4 + 255) / 256, 256>>>(W_out, 1, CC * CC / 4);

    {
        dim3 grid(E3 / 128, MM / 128);   // (24, 32)
        tc_gemm<0><<<grid, 512, GSMEM>>>(x, nullptr, nullptr);
    }
    {
        dim3 grid(NN / 128, BH);         // (16, 32)
        attn_mma_kernel<<<grid, 256, ATT_SMEM>>>();
    }
    {
        dim3 grid(CC / 128, MM / 128);   // (8, 32)
        tc_gemm<1><<<grid, 512, GSMEM>>>(nullptr, b_out, out);
    }
}

// round 13
// speedup vs baseline: 1.4319x; 1.1461x over previous
#include <cuda_runtime.h>
#include <cuda_fp16.h>
#include <cstdint>
#include <math.h>

#define BB 2
#define NN 2048
#define CC 1024
#define HH 16
#define DD 64
#define E3 3072
#define MM (BB*NN)   // 4096
#define BH (BB*HH)   // 32

// Q scale: 1/sqrt(64) * log2(e)  (scores computed in log2 domain for ex2.approx)
#define QSCALE 0.1803368801111204f

// ---------------- scratch (no allocations allowed) ----------------
__device__ __half g_qh[BH * NN * DD];                      // Q: fp16 hi only (pre-scaled)
__device__ __half g_kh[BH * NN * DD], g_kl[BH * NN * DD];
__device__ __half g_vh[BH * NN * DD], g_vl[BH * NN * DD];
__device__ __half g_aoh[MM * CC],    g_aol[MM * CC];
__device__ __half g_wqh[E3 * CC];                          // weights: hi only (2-term GEMM)
__device__ __half g_woh[CC * CC];

__device__ __forceinline__ float ex2f(float x) {
    float r;
    asm("ex2.approx.f32 %0, %1;" : "=f"(r) : "f"(x));
    return r;
}
__device__ __forceinline__ uint32_t smem_u32(const void* p) {
    uint32_t a;
    asm("{ .reg .u64 t; cvta.to.shared.u64 t, %1; cvt.u32.u64 %0, t; }" : "=r"(a) : "l"(p));
    return a;
}
__device__ __forceinline__ void mma16816(float* c, const uint32_t* a, const uint32_t* b) {
    asm volatile("mma.sync.aligned.m16n8k16.row.col.f32.f16.f16.f32 "
        "{%0,%1,%2,%3}, {%4,%5,%6,%7}, {%8,%9}, {%0,%1,%2,%3};"
        : "+f"(c[0]), "+f"(c[1]), "+f"(c[2]), "+f"(c[3])
        : "r"(a[0]), "r"(a[1]), "r"(a[2]), "r"(a[3]), "r"(b[0]), "r"(b[1]));
}
__device__ __forceinline__ void ldsm_x4(uint32_t* r, uint32_t addr) {
    asm volatile("ldmatrix.sync.aligned.m8n8.x4.shared.b16 {%0,%1,%2,%3}, [%4];"
        : "=r"(r[0]), "=r"(r[1]), "=r"(r[2]), "=r"(r[3]) : "r"(addr));
}
__device__ __forceinline__ void ldsm_x2(uint32_t* r, uint32_t addr) {
    asm volatile("ldmatrix.sync.aligned.m8n8.x2.shared.b16 {%0,%1}, [%2];"
        : "=r"(r[0]), "=r"(r[1]) : "r"(addr));
}
__device__ __forceinline__ void ldsm_x2t(uint32_t* r, uint32_t addr) {
    asm volatile("ldmatrix.sync.aligned.m8n8.x2.trans.shared.b16 {%0,%1}, [%2];"
        : "=r"(r[0]), "=r"(r[1]) : "r"(addr));
}
__device__ __forceinline__ uint32_t packh2(__half a, __half b) {
    __half2 t = __halves2half2(a, b);
    return *reinterpret_cast<uint32_t*>(&t);
}
__device__ __forceinline__ void cvt_split(float4 v, uint2& h, uint2& l) {
    __half h0 = __float2half_rn(v.x), h1 = __float2half_rn(v.y);
    __half h2 = __float2half_rn(v.z), h3 = __float2half_rn(v.w);
    h.x = packh2(h0, h1); h.y = packh2(h2, h3);
    l.x = packh2(__float2half_rn(v.x - __half2float(h0)),
                 __float2half_rn(v.y - __half2float(h1)));
    l.y = packh2(__float2half_rn(v.z - __half2float(h2)),
                 __float2half_rn(v.w - __half2float(h3)));
}
__device__ __forceinline__ void split2(float x, float y, __half2& h, __half2& l) {
    __half hx = __float2half_rn(x), hy = __float2half_rn(y);
    h = __halves2half2(hx, hy);
    l = __halves2half2(__float2half_rn(x - __half2float(hx)),
                       __float2half_rn(y - __half2float(hy)));
}
__device__ __forceinline__ void cp16(uint32_t saddr, const void* gaddr) {
    asm volatile("cp.async.cg.shared.global [%0], [%1], 16;" :: "r"(saddr), "l"(gaddr));
}
#define CP_COMMIT() asm volatile("cp.async.commit_group;" ::: "memory")
#define CP_WAIT0()  asm volatile("cp.async.wait_group 0;" ::: "memory")
#define CP_WAIT1()  asm volatile("cp.async.wait_group 1;" ::: "memory")

// ---------------- weight conversion: fp32 -> fp16 hi only ----------------
__global__ __launch_bounds__(256) void whalf_kernel(const float* __restrict__ src,
                                                    int which, int n4)
{
    __half* hi = (which == 0) ? g_wqh : g_woh;
    int i = blockIdx.x * blockDim.x + threadIdx.x;
    if (i >= n4) return;
    float4 a = ((const float4*)src)[i];
    uint2 h;
    h.x = packh2(__float2half_rn(a.x), __float2half_rn(a.y));
    h.y = packh2(__float2half_rn(a.z), __float2half_rn(a.w));
    *(uint2*)(hi + (size_t)i * 4) = h;
}

// ---------------- mma.sync 2-term GEMM: AhBh + AlBh ----------------
// A keeps hi+lo (full precision), B = weights hi only.
// Tile 128x128, BK=32, 512 threads, double-buffered.
// smem stage (halves): Ah @0, Al @5120, Bh @10240; stage stride 15360 (30720 B).
#define GSMEM 61440
template<int MODE>
__global__ __launch_bounds__(512) void tc_gemm(const float* __restrict__ Ain,
                                               const float* __restrict__ bias,
                                               float* __restrict__ outp)
{
    extern __shared__ __half sm[];
    const int tid  = threadIdx.x;
    const int lane = tid & 31;
    const int wid  = tid >> 5;
    const int wm   = wid >> 2;
    const int wn   = wid & 3;
    const int m0 = blockIdx.y * 128;
    const int n0 = blockIdx.x * 128;

    const __half* pBh = (MODE == 0) ? g_wqh : g_woh;

    const uint32_t sbase = smem_u32(sm);
    const uint32_t a_row = wm * 32 + (lane & 15);
    const uint32_t a_kg  = (lane >> 4) << 3;
    const uint32_t b_kg  = ((lane >> 3) & 1) << 3;

    const int brow = tid >> 2;
    const int bkgc = (tid & 3) * 8;
    const __half* gBh = pBh + (size_t)(n0 + brow) * CC + bkgc;
    const __half* gAh = g_aoh + (size_t)(m0 + brow) * CC + bkgc;   // MODE 1 only
    const __half* gAl = g_aol + (size_t)(m0 + brow) * CC + bkgc;
    const uint32_t coff = (uint32_t)(brow * 40 + bkgc) * 2;

    float acc[2][4][4];
#pragma unroll
    for (int i = 0; i < 2; i++)
#pragma unroll
        for (int j = 0; j < 4; j++)
#pragma unroll
            for (int c = 0; c < 4; c++) acc[i][j][c] = 0.0f;

    float4 ra[2];
    if (MODE == 0) {
#pragma unroll
        for (int i = 0; i < 2; i++) {
            int slot = tid + i * 512;
            int row = slot >> 3, c4 = (slot & 7) * 4;
            ra[i] = *(const float4*)&Ain[(size_t)(m0 + row) * CC + c4];
        }
    }

    auto store_A = [&](int st) {
#pragma unroll
        for (int i = 0; i < 2; i++) {
            int slot = tid + i * 512;
            int row = slot >> 3, c = (slot & 7) * 4;
            uint2 h, l;
            cvt_split(ra[i], h, l);
            *(uint2*)&sm[st * 15360 +        row * 40 + c] = h;
            *(uint2*)&sm[st * 15360 + 5120 + row * 40 + c] = l;
        }
    };
    auto issue_tiles = [&](int st, int k0) {
        uint32_t base = sbase + st * 30720;
        cp16(base + 20480 + coff, gBh + k0);
        if (MODE == 1) {
            cp16(base +         coff, gAh + k0);
            cp16(base + 10240 + coff, gAl + k0);
        }
    };

    issue_tiles(0, 0);
    CP_COMMIT();
    if (MODE == 0) store_A(0);
    CP_WAIT0();
    __syncthreads();

    for (int k0 = 0; k0 < CC; k0 += 32) {
        const int st   = (k0 >> 5) & 1;
        const bool nxt = (k0 + 32 < CC);

        if (nxt) {
            issue_tiles(st ^ 1, k0 + 32);
            CP_COMMIT();
            if (MODE == 0) {
#pragma unroll
                for (int i = 0; i < 2; i++) {
                    int slot = tid + i * 512;
                    int row = slot >> 3, c4 = (slot & 7) * 4;
                    ra[i] = *(const float4*)&Ain[(size_t)(m0 + row) * CC + k0 + 32 + c4];
                }
            }
        }

        const uint32_t base = sbase + st * 30720;
#pragma unroll
        for (int ks = 0; ks < 2; ks++) {
            const uint32_t kcol = ks * 16;
            uint32_t ah[2][4], al[2][4];
#pragma unroll
            for (int mt = 0; mt < 2; mt++) {
                uint32_t off = ((a_row + mt * 16) * 40 + kcol + a_kg) * 2;
                ldsm_x4(ah[mt], base + off);
                ldsm_x4(al[mt], base + 10240 + off);
            }
#pragma unroll
            for (int nt = 0; nt < 4; nt++) {
                uint32_t boff = ((wn * 32 + nt * 8 + (lane & 7)) * 40 + kcol + b_kg) * 2;
                uint32_t bhr[2];
                ldsm_x2(bhr, base + 20480 + boff);
#pragma unroll
                for (int mt = 0; mt < 2; mt++) {
                    mma16816(acc[mt][nt], ah[mt], bhr);
                    mma16816(acc[mt][nt], al[mt], bhr);
                }
            }
            if (MODE == 0 && ks == 0 && nxt) store_A(st ^ 1);
        }

        if (nxt) CP_WAIT0();
        __syncthreads();
    }

    // Epilogue
#pragma unroll
    for (int mt = 0; mt < 2; mt++) {
#pragma unroll
        for (int nt = 0; nt < 4; nt++) {
            const float* c = acc[mt][nt];
            const int col = n0 + wn * 32 + nt * 8 + (lane & 3) * 2;
#pragma unroll
            for (int hr = 0; hr < 2; hr++) {
                const int row = m0 + wm * 32 + mt * 16 + (lane >> 2) + hr * 8;
                float vx = c[hr * 2 + 0], vy = c[hr * 2 + 1];
                if (MODE == 0) {
                    const int part = col >> 10, rr = col & 1023;
                    const int h = rr >> 6, d = rr & 63;
                    const int b = row >> 11, n = row & 2047;
                    const size_t addr = ((size_t)(b * HH + h) * NN + n) * DD + d;
                    if (part == 0) {
                        vx *= QSCALE; vy *= QSCALE;
                        __half2 hh, ll;
                        split2(vx, vy, hh, ll);
                        *(__half2*)&g_qh[addr] = hh;          // hi only
                    } else {
                        __half* dh = (part == 1) ? g_kh : g_vh;
                        __half* dl = (part == 1) ? g_kl : g_vl;
                        __half2 hh, ll;
                        split2(vx, vy, hh, ll);
                        *(__half2*)&dh[addr] = hh;
                        *(__half2*)&dl[addr] = ll;
                    }
                } else {
                    vx += bias[col];
                    vy += bias[col + 1];
                    *(float2*)&outp[(size_t)row * CC + col] = make_float2(vx, vy);
                }
            }
        }
    }
}

// ---------------- MMA flash attention: 2-term QK, 2-term PV, 2 CTAs/SM --------
// Smem: 2 stages x (Kh|Kl|Vh|Vl)[64][72] = 73728 B. Qh staging overlays stage 0.
#define ATT_SMEM 73728
__global__ __launch_bounds__(256, 2) void attn_mma_kernel()
{
    extern __shared__ __half smh[];
    const int bh   = blockIdx.y;
    const int q0   = blockIdx.x * 128;
    const int tid  = threadIdx.x;
    const int lane = tid & 31;
    const int warp = tid >> 5;

    const uint32_t sbase = smem_u32(smh);
    const size_t hb = (size_t)bh * NN * DD;
    const __half* kvsrc[4] = { g_kh + hb, g_kl + hb, g_vh + hb, g_vl + hb };

    // ---- prologue: Qh (stage-0 region) + KV tile 0 (stage-1 region) ----
#pragma unroll
    for (int i = 0; i < 4; i++) {
        const int s = tid + i * 256;
        const int row = s >> 3, c = (s & 7) * 8;
        cp16(sbase + (row * 72 + c) * 2, g_qh + hb + (size_t)(q0 + row) * DD + c);
    }
    CP_COMMIT();
#pragma unroll
    for (int i = 0; i < 8; i++) {
        const int mat = i >> 1;
        const int s = tid + (i & 1) * 256;
        const int row = s >> 3, c = (s & 7) * 8;
        cp16(sbase + 36864 + mat * 9216 + (row * 72 + c) * 2,
             kvsrc[mat] + (size_t)row * DD + c);
    }
    CP_COMMIT();
    CP_WAIT1();
    __syncthreads();

    // ---- Q fragments (hi only) ----
    uint32_t qh[4][4];
    {
        const uint32_t arow = warp * 16 + (lane & 15);
        const uint32_t akg  = ((lane >> 4) & 1) * 8;
#pragma unroll
        for (int ks = 0; ks < 4; ks++)
            ldsm_x4(qh[ks], sbase + (arow * 72 + ks * 16 + akg) * 2);
    }
    __syncthreads();

    float O[8][4];
#pragma unroll
    for (int n = 0; n < 8; n++)
#pragma unroll
        for (int c = 0; c < 4; c++) O[n][c] = 0.0f;
    float m0r = -1e30f, m1r = -1e30f;
    float l0 = 0.0f, l1 = 0.0f;

    const uint32_t bkey = (lane & 7);
    const uint32_t bkg  = ((lane >> 3) & 1) * 8;
    const uint32_t vrow = (lane & 15);

    for (int t = 0; t < 32; t++) {
        const uint32_t base = sbase + ((t & 1) ? 0u : 36864u);

        if (t + 1 < 32) {
            const uint32_t nbase = sbase + ((t & 1) ? 36864u : 0u);
            const int j0 = (t + 1) * 64;
#pragma unroll
            for (int i = 0; i < 8; i++) {
                const int mat = i >> 1;
                const int s = tid + (i & 1) * 256;
                const int row = s >> 3, c = (s & 7) * 8;
                cp16(nbase + mat * 9216 + (row * 72 + c) * 2,
                     kvsrc[mat] + (size_t)(j0 + row) * DD + c);
            }
            CP_COMMIT();
            CP_WAIT1();
        } else {
            CP_WAIT0();
        }
        __syncthreads();

        // ---- scores: QhKh + QhKl (log2 domain) ----
        float s[8][4];
#pragma unroll
        for (int n = 0; n < 8; n++)
#pragma unroll
            for (int c = 0; c < 4; c++) s[n][c] = 0.0f;

#pragma unroll
        for (int ks = 0; ks < 4; ks++) {
#pragma unroll
            for (int nt = 0; nt < 8; nt++) {
                uint32_t boff = ((nt * 8 + bkey) * 72 + ks * 16 + bkg) * 2;
                uint32_t kbh[2], kbl[2];
                ldsm_x2(kbh, base + boff);
                ldsm_x2(kbl, base + 9216 + boff);
                mma16816(s[nt], qh[ks], kbh);
                mma16816(s[nt], qh[ks], kbl);
            }
        }

        // ---- online softmax (exp2) ----
        float mloc0 = -1e30f, mloc1 = -1e30f;
#pragma unroll
        for (int nt = 0; nt < 8; nt++) {
            mloc0 = fmaxf(mloc0, fmaxf(s[nt][0], s[nt][1]));
            mloc1 = fmaxf(mloc1, fmaxf(s[nt][2], s[nt][3]));
        }
        mloc0 = fmaxf(mloc0, __shfl_xor_sync(0xffffffffu, mloc0, 1));
        mloc0 = fmaxf(mloc0, __shfl_xor_sync(0xffffffffu, mloc0, 2));
        mloc1 = fmaxf(mloc1, __shfl_xor_sync(0xffffffffu, mloc1, 1));
        mloc1 = fmaxf(mloc1, __shfl_xor_sync(0xffffffffu, mloc1, 2));

        float mn0 = fmaxf(m0r, mloc0), mn1 = fmaxf(m1r, mloc1);
        float cr0 = ex2f(m0r - mn0), cr1 = ex2f(m1r - mn1);
        m0r = mn0; m1r = mn1;
        l0 *= cr0; l1 *= cr1;
#pragma unroll
        for (int n = 0; n < 8; n++) {
            O[n][0] *= cr0; O[n][1] *= cr0;
            O[n][2] *= cr1; O[n][3] *= cr1;
        }

        float ls0 = 0.0f, ls1 = 0.0f;
        uint32_t aPh[4][4];
#pragma unroll
        for (int nt = 0; nt < 8; nt++) {
            float p0 = ex2f(s[nt][0] - m0r);
            float p1 = ex2f(s[nt][1] - m0r);
            float p2 = ex2f(s[nt][2] - m1r);
            float p3 = ex2f(s[nt][3] - m1r);
            ls0 += p0 + p1; ls1 += p2 + p3;
            const int kt = nt >> 1, hi2 = (nt & 1) * 2;
            aPh[kt][hi2 + 0] = packh2(__float2half_rn(p0), __float2half_rn(p1));
            aPh[kt][hi2 + 1] = packh2(__float2half_rn(p2), __float2half_rn(p3));
        }
        ls0 += __shfl_xor_sync(0xffffffffu, ls0, 1);
        ls0 += __shfl_xor_sync(0xffffffffu, ls0, 2);
        ls1 += __shfl_xor_sync(0xffffffffu, ls1, 1);
        ls1 += __shfl_xor_sync(0xffffffffu, ls1, 2);
        l0 += ls0; l1 += ls1;

        // ---- O += PhVh + PhVl ----
#pragma unroll
        for (int kt = 0; kt < 4; kt++) {
#pragma unroll
            for (int nd = 0; nd < 8; nd++) {
                uint32_t voff = ((kt * 16 + vrow) * 72 + nd * 8) * 2;
                uint32_t vbh[2], vbl[2];
                ldsm_x2t(vbh, base + 18432 + voff);
                ldsm_x2t(vbl, base + 27648 + voff);
                mma16816(O[nd], aPh[kt], vbh);
                mma16816(O[nd], aPh[kt], vbl);
            }
        }
        __syncthreads();
    }

    // ---- epilogue: hi/lo attention output ----
    const float inv0 = 1.0f / l0, inv1 = 1.0f / l1;
    const int b = bh >> 4, h = bh & 15;
    const int row0 = q0 + warp * 16 + (lane >> 2);
    const int row1 = row0 + 8;
#pragma unroll
    for (int nd = 0; nd < 8; nd++) {
        const int d = nd * 8 + (lane & 3) * 2;
        const size_t a0 = ((size_t)(b * NN + row0)) * CC + h * DD + d;
        const size_t a1 = ((size_t)(b * NN + row1)) * CC + h * DD + d;
        __half2 hh, ll;
        split2(O[nd][0] * inv0, O[nd][1] * inv0, hh, ll);
        *(__half2*)&g_aoh[a0] = hh;
        *(__half2*)&g_aol[a0] = ll;
        split2(O[nd][2] * inv1, O[nd][3] * inv1, hh, ll);
        *(__half2*)&g_aoh[a1] = hh;
        *(__half2*)&g_aol[a1] = ll;
    }
}

// ---------------------------------------------------------------------------
extern "C" void kernel_launch(void* const* d_in, const int* in_sizes, int n_in,
                              void* d_out, int out_size)
{
    const float* x     = (const float*)d_in[0];
    const float* W_qkv = (const float*)d_in[1];
    const float* W_out = (const float*)d_in[2];
    const float* b_out = (const float*)d_in[3];
    float* out = (float*)d_out;
    (void)in_sizes; (void)n_in; (void)out_size;

    cudaFuncSetAttribute(tc_gemm<0>, cudaFuncAttributeMaxDynamicSharedMemorySize, GSMEM);
    cudaFuncSetAttribute(tc_gemm<1>, cudaFuncAttributeMaxDynamicSharedMemorySize, GSMEM);
    cudaFuncSetAttribute(attn_mma_kernel, cudaFuncAttributeMaxDynamicSharedMemorySize, ATT_SMEM);

    whalf_kernel<<<(E3 * CC / 4 + 255) / 256, 256>>>(W_qkv, 0, E3 * CC / 4);
    whalf_kernel<<<(CC * CC / 4 + 255) / 256, 256>>>(W_out, 1, CC * CC / 4);

    {
        dim3 grid(E3 / 128, MM / 128);   // (24, 32)
        tc_gemm<0><<<grid, 512, GSMEM>>>(x, nullptr, nullptr);
    }
    {
        dim3 grid(NN / 128, BH);         // (16, 32)
        attn_mma_kernel<<<grid, 256, ATT_SMEM>>>();
    }
    {
        dim3 grid(CC / 128, MM / 128);   // (8, 32)
        tc_gemm<1><<<grid, 512, GSMEM>>>(nullptr, b_out, out);
    }
}

// round 14
// speedup vs baseline: 2.2250x; 1.5539x over previous
#include <cuda_runtime.h>
#include <cuda_fp16.h>
#include <cstdint>
#include <math.h>

#define BB 2
#define NN 2048
#define CC 1024
#define HH 16
#define DD 64
#define E3 3072
#define MM (BB*NN)   // 4096
#define BH (BB*HH)   // 32

// Q scale: 1/sqrt(64) * log2(e)  (scores in log2 domain for ex2.approx)
#define QSCALE 0.1803368801111204f

// ---------------- scratch (no allocations allowed) ----------------
__device__ __half g_qh[BH * NN * DD];                   // Q fp16 (pre-scaled)
__device__ __half g_kh[BH * NN * DD];                   // K fp16
__device__ __half g_vh[BH * NN * DD];                   // V fp16
__device__ __half g_aoh[MM * CC], g_aol[MM * CC];       // attention out hi/lo
__device__ __half g_wqh[E3 * CC];                       // weights fp16
__device__ __half g_woh[CC * CC];

__device__ __forceinline__ float ex2f(float x) {
    float r;
    asm("ex2.approx.f32 %0, %1;" : "=f"(r) : "f"(x));
    return r;
}
__device__ __forceinline__ uint32_t smem_u32(const void* p) {
    uint32_t a;
    asm("{ .reg .u64 t; cvta.to.shared.u64 t, %1; cvt.u32.u64 %0, t; }" : "=r"(a) : "l"(p));
    return a;
}
__device__ __forceinline__ void mma16816(float* c, const uint32_t* a, const uint32_t* b) {
    asm volatile("mma.sync.aligned.m16n8k16.row.col.f32.f16.f16.f32 "
        "{%0,%1,%2,%3}, {%4,%5,%6,%7}, {%8,%9}, {%0,%1,%2,%3};"
        : "+f"(c[0]), "+f"(c[1]), "+f"(c[2]), "+f"(c[3])
        : "r"(a[0]), "r"(a[1]), "r"(a[2]), "r"(a[3]), "r"(b[0]), "r"(b[1]));
}
__device__ __forceinline__ void ldsm_x4(uint32_t* r, uint32_t addr) {
    asm volatile("ldmatrix.sync.aligned.m8n8.x4.shared.b16 {%0,%1,%2,%3}, [%4];"
        : "=r"(r[0]), "=r"(r[1]), "=r"(r[2]), "=r"(r[3]) : "r"(addr));
}
__device__ __forceinline__ void ldsm_x2(uint32_t* r, uint32_t addr) {
    asm volatile("ldmatrix.sync.aligned.m8n8.x2.shared.b16 {%0,%1}, [%2];"
        : "=r"(r[0]), "=r"(r[1]) : "r"(addr));
}
__device__ __forceinline__ void ldsm_x2t(uint32_t* r, uint32_t addr) {
    asm volatile("ldmatrix.sync.aligned.m8n8.x2.trans.shared.b16 {%0,%1}, [%2];"
        : "=r"(r[0]), "=r"(r[1]) : "r"(addr));
}
__device__ __forceinline__ uint32_t packh2(__half a, __half b) {
    __half2 t = __halves2half2(a, b);
    return *reinterpret_cast<uint32_t*>(&t);
}
__device__ __forceinline__ void cvt_hi(float4 v, uint2& h) {
    h.x = packh2(__float2half_rn(v.x), __float2half_rn(v.y));
    h.y = packh2(__float2half_rn(v.z), __float2half_rn(v.w));
}
__device__ __forceinline__ void split2(float x, float y, __half2& h, __half2& l) {
    __half hx = __float2half_rn(x), hy = __float2half_rn(y);
    h = __halves2half2(hx, hy);
    l = __halves2half2(__float2half_rn(x - __half2float(hx)),
                       __float2half_rn(y - __half2float(hy)));
}
__device__ __forceinline__ void cp16(uint32_t saddr, const void* gaddr) {
    asm volatile("cp.async.cg.shared.global [%0], [%1], 16;" :: "r"(saddr), "l"(gaddr));
}
#define CP_COMMIT() asm volatile("cp.async.commit_group;" ::: "memory")
#define CP_WAIT0()  asm volatile("cp.async.wait_group 0;" ::: "memory")
#define CP_WAIT1()  asm volatile("cp.async.wait_group 1;" ::: "memory")

// ---------------- weight conversion: fp32 -> fp16 ----------------
__global__ __launch_bounds__(256) void whalf_kernel(const float* __restrict__ src,
                                                    int which, int n4)
{
    __half* hi = (which == 0) ? g_wqh : g_woh;
    int i = blockIdx.x * blockDim.x + threadIdx.x;
    if (i >= n4) return;
    float4 a = ((const float4*)src)[i];
    uint2 h;
    cvt_hi(a, h);
    *(uint2*)(hi + (size_t)i * 4) = h;
}

// ---------------- mma.sync GEMM ----------------
// MODE 0 (qkv): 1-term AhBh. A = x fp32 -> fp16 inline. Epilogue: Q/K/V fp16.
// MODE 1 (proj): 2-term AhBh + AlBh. A = ao hi/lo via cp.async. Out fp32 + bias.
// smem stage (halves): Ah @0, Al @5120 (MODE 1), Bh @10240; stage stride 15360.
#define GSMEM 61440
template<int MODE>
__global__ __launch_bounds__(512) void tc_gemm(const float* __restrict__ Ain,
                                               const float* __restrict__ bias,
                                               float* __restrict__ outp)
{
    extern __shared__ __half sm[];
    const int tid  = threadIdx.x;
    const int lane = tid & 31;
    const int wid  = tid >> 5;
    const int wm   = wid >> 2;
    const int wn   = wid & 3;
    const int m0 = blockIdx.y * 128;
    const int n0 = blockIdx.x * 128;

    const __half* pBh = (MODE == 0) ? g_wqh : g_woh;

    const uint32_t sbase = smem_u32(sm);
    const uint32_t a_row = wm * 32 + (lane & 15);
    const uint32_t a_kg  = (lane >> 4) << 3;
    const uint32_t b_kg  = ((lane >> 3) & 1) << 3;

    const int brow = tid >> 2;
    const int bkgc = (tid & 3) * 8;
    const __half* gBh = pBh + (size_t)(n0 + brow) * CC + bkgc;
    const __half* gAh = g_aoh + (size_t)(m0 + brow) * CC + bkgc;   // MODE 1
    const __half* gAl = g_aol + (size_t)(m0 + brow) * CC + bkgc;
    const uint32_t coff = (uint32_t)(brow * 40 + bkgc) * 2;

    float acc[2][4][4];
#pragma unroll
    for (int i = 0; i < 2; i++)
#pragma unroll
        for (int j = 0; j < 4; j++)
#pragma unroll
            for (int c = 0; c < 4; c++) acc[i][j][c] = 0.0f;

    float4 ra[2];
    if (MODE == 0) {
#pragma unroll
        for (int i = 0; i < 2; i++) {
            int slot = tid + i * 512;
            int row = slot >> 3, c4 = (slot & 7) * 4;
            ra[i] = *(const float4*)&Ain[(size_t)(m0 + row) * CC + c4];
        }
    }

    auto store_A = [&](int st) {
#pragma unroll
        for (int i = 0; i < 2; i++) {
            int slot = tid + i * 512;
            int row = slot >> 3, c = (slot & 7) * 4;
            uint2 h;
            cvt_hi(ra[i], h);
            *(uint2*)&sm[st * 15360 + row * 40 + c] = h;
        }
    };
    auto issue_tiles = [&](int st, int k0) {
        uint32_t base = sbase + st * 30720;
        cp16(base + 20480 + coff, gBh + k0);
        if (MODE == 1) {
            cp16(base +         coff, gAh + k0);
            cp16(base + 10240 + coff, gAl + k0);
        }
    };

    issue_tiles(0, 0);
    CP_COMMIT();
    if (MODE == 0) store_A(0);
    CP_WAIT0();
    __syncthreads();

    for (int k0 = 0; k0 < CC; k0 += 32) {
        const int st   = (k0 >> 5) & 1;
        const bool nxt = (k0 + 32 < CC);

        if (nxt) {
            issue_tiles(st ^ 1, k0 + 32);
            CP_COMMIT();
            if (MODE == 0) {
#pragma unroll
                for (int i = 0; i < 2; i++) {
                    int slot = tid + i * 512;
                    int row = slot >> 3, c4 = (slot & 7) * 4;
                    ra[i] = *(const float4*)&Ain[(size_t)(m0 + row) * CC + k0 + 32 + c4];
                }
            }
        }

        const uint32_t base = sbase + st * 30720;
#pragma unroll
        for (int ks = 0; ks < 2; ks++) {
            const uint32_t kcol = ks * 16;
            uint32_t ah[2][4], al[2][4];
#pragma unroll
            for (int mt = 0; mt < 2; mt++) {
                uint32_t off = ((a_row + mt * 16) * 40 + kcol + a_kg) * 2;
                ldsm_x4(ah[mt], base + off);
                if (MODE == 1) ldsm_x4(al[mt], base + 10240 + off);
            }
#pragma unroll
            for (int nt = 0; nt < 4; nt++) {
                uint32_t boff = ((wn * 32 + nt * 8 + (lane & 7)) * 40 + kcol + b_kg) * 2;
                uint32_t bhr[2];
                ldsm_x2(bhr, base + 20480 + boff);
#pragma unroll
                for (int mt = 0; mt < 2; mt++) {
                    mma16816(acc[mt][nt], ah[mt], bhr);
                    if (MODE == 1) mma16816(acc[mt][nt], al[mt], bhr);
                }
            }
            if (MODE == 0 && ks == 0 && nxt) store_A(st ^ 1);
        }

        if (nxt) CP_WAIT0();
        __syncthreads();
    }

    // Epilogue
#pragma unroll
    for (int mt = 0; mt < 2; mt++) {
#pragma unroll
        for (int nt = 0; nt < 4; nt++) {
            const float* c = acc[mt][nt];
            const int col = n0 + wn * 32 + nt * 8 + (lane & 3) * 2;
#pragma unroll
            for (int hr = 0; hr < 2; hr++) {
                const int row = m0 + wm * 32 + mt * 16 + (lane >> 2) + hr * 8;
                float vx = c[hr * 2 + 0], vy = c[hr * 2 + 1];
                if (MODE == 0) {
                    const int part = col >> 10, rr = col & 1023;
                    const int h = rr >> 6, d = rr & 63;
                    const int b = row >> 11, n = row & 2047;
                    const size_t addr = ((size_t)(b * HH + h) * NN + n) * DD + d;
                    if (part == 0) { vx *= QSCALE; vy *= QSCALE; }
                    __half* dst = (part == 0) ? g_qh : (part == 1) ? g_kh : g_vh;
                    *(__half2*)&dst[addr] =
                        __halves2half2(__float2half_rn(vx), __float2half_rn(vy));
                } else {
                    vx += bias[col];
                    vy += bias[col + 1];
                    *(float2*)&outp[(size_t)row * CC + col] = make_float2(vx, vy);
                }
            }
        }
    }
}

// ---------------- MMA flash attention: pure fp16, 1-term QK + 1-term PV ------
// Smem: 2 stages x (Kh|Vh)[64][72] = 36864 B. Qh staging overlays stage 0.
// Stage stride 18432 B; Kh @0, Vh @9216 within stage.
#define ATT_SMEM 36864
__global__ __launch_bounds__(256, 2) void attn_mma_kernel()
{
    extern __shared__ __half smh[];
    const int bh   = blockIdx.y;
    const int q0   = blockIdx.x * 128;
    const int tid  = threadIdx.x;
    const int lane = tid & 31;
    const int warp = tid >> 5;

    const uint32_t sbase = smem_u32(smh);
    const size_t hb = (size_t)bh * NN * DD;
    const __half* kvsrc[2] = { g_kh + hb, g_vh + hb };

    // ---- prologue: Qh (stage-0 region, 18432 B) + KV tile 0 (stage 1) ----
#pragma unroll
    for (int i = 0; i < 4; i++) {
        const int s = tid + i * 256;            // 1024 chunks (128 rows x 8)
        const int row = s >> 3, c = (s & 7) * 8;
        cp16(sbase + (row * 72 + c) * 2, g_qh + hb + (size_t)(q0 + row) * DD + c);
    }
    CP_COMMIT();
#pragma unroll
    for (int i = 0; i < 4; i++) {
        const int mat = i >> 1;                 // 0: Kh, 1: Vh
        const int s = tid + (i & 1) * 256;      // 512 chunks per matrix
        const int row = s >> 3, c = (s & 7) * 8;
        cp16(sbase + 18432 + mat * 9216 + (row * 72 + c) * 2,
             kvsrc[mat] + (size_t)row * DD + c);
    }
    CP_COMMIT();
    CP_WAIT1();
    __syncthreads();

    // ---- Q fragments ----
    uint32_t qh[4][4];
    {
        const uint32_t arow = warp * 16 + (lane & 15);
        const uint32_t akg  = ((lane >> 4) & 1) * 8;
#pragma unroll
        for (int ks = 0; ks < 4; ks++)
            ldsm_x4(qh[ks], sbase + (arow * 72 + ks * 16 + akg) * 2);
    }
    __syncthreads();   // Q region free for tile 1

    float O[8][4];
#pragma unroll
    for (int n = 0; n < 8; n++)
#pragma unroll
        for (int c = 0; c < 4; c++) O[n][c] = 0.0f;
    float m0r = -1e30f, m1r = -1e30f;
    float l0 = 0.0f, l1 = 0.0f;

    const uint32_t bkey = (lane & 7);
    const uint32_t bkg  = ((lane >> 3) & 1) * 8;
    const uint32_t vrow = (lane & 15);

    for (int t = 0; t < 32; t++) {
        const uint32_t base = sbase + ((t & 1) ? 0u : 18432u);

        if (t + 1 < 32) {
            const uint32_t nbase = sbase + ((t & 1) ? 18432u : 0u);
            const int j0 = (t + 1) * 64;
#pragma unroll
            for (int i = 0; i < 4; i++) {
                const int mat = i >> 1;
                const int s = tid + (i & 1) * 256;
                const int row = s >> 3, c = (s & 7) * 8;
                cp16(nbase + mat * 9216 + (row * 72 + c) * 2,
                     kvsrc[mat] + (size_t)(j0 + row) * DD + c);
            }
            CP_COMMIT();
            CP_WAIT1();
        } else {
            CP_WAIT0();
        }
        __syncthreads();

        // ---- scores: QhKh (log2 domain) ----
        float s[8][4];
#pragma unroll
        for (int n = 0; n < 8; n++)
#pragma unroll
            for (int c = 0; c < 4; c++) s[n][c] = 0.0f;

#pragma unroll
        for (int ks = 0; ks < 4; ks++) {
#pragma unroll
            for (int nt = 0; nt < 8; nt++) {
                uint32_t boff = ((nt * 8 + bkey) * 72 + ks * 16 + bkg) * 2;
                uint32_t kbh[2];
                ldsm_x2(kbh, base + boff);
                mma16816(s[nt], qh[ks], kbh);
            }
        }

        // ---- online softmax (exp2) ----
        float mloc0 = -1e30f, mloc1 = -1e30f;
#pragma unroll
        for (int nt = 0; nt < 8; nt++) {
            mloc0 = fmaxf(mloc0, fmaxf(s[nt][0], s[nt][1]));
            mloc1 = fmaxf(mloc1, fmaxf(s[nt][2], s[nt][3]));
        }
        mloc0 = fmaxf(mloc0, __shfl_xor_sync(0xffffffffu, mloc0, 1));
        mloc0 = fmaxf(mloc0, __shfl_xor_sync(0xffffffffu, mloc0, 2));
        mloc1 = fmaxf(mloc1, __shfl_xor_sync(0xffffffffu, mloc1, 1));
        mloc1 = fmaxf(mloc1, __shfl_xor_sync(0xffffffffu, mloc1, 2));

        float mn0 = fmaxf(m0r, mloc0), mn1 = fmaxf(m1r, mloc1);
        float cr0 = ex2f(m0r - mn0), cr1 = ex2f(m1r - mn1);
        m0r = mn0; m1r = mn1;
        l0 *= cr0; l1 *= cr1;
#pragma unroll
        for (int n = 0; n < 8; n++) {
            O[n][0] *= cr0; O[n][1] *= cr0;
            O[n][2] *= cr1; O[n][3] *= cr1;
        }

        float ls0 = 0.0f, ls1 = 0.0f;
        uint32_t aPh[4][4];
#pragma unroll
        for (int nt = 0; nt < 8; nt++) {
            float p0 = ex2f(s[nt][0] - m0r);
            float p1 = ex2f(s[nt][1] - m0r);
            float p2 = ex2f(s[nt][2] - m1r);
            float p3 = ex2f(s[nt][3] - m1r);
            ls0 += p0 + p1; ls1 += p2 + p3;
            const int kt = nt >> 1, hi2 = (nt & 1) * 2;
            aPh[kt][hi2 + 0] = packh2(__float2half_rn(p0), __float2half_rn(p1));
            aPh[kt][hi2 + 1] = packh2(__float2half_rn(p2), __float2half_rn(p3));
        }
        ls0 += __shfl_xor_sync(0xffffffffu, ls0, 1);
        ls0 += __shfl_xor_sync(0xffffffffu, ls0, 2);
        ls1 += __shfl_xor_sync(0xffffffffu, ls1, 1);
        ls1 += __shfl_xor_sync(0xffffffffu, ls1, 2);
        l0 += ls0; l1 += ls1;

        // ---- O += PhVh ----
#pragma unroll
        for (int kt = 0; kt < 4; kt++) {
#pragma unroll
            for (int nd = 0; nd < 8; nd++) {
                uint32_t voff = ((kt * 16 + vrow) * 72 + nd * 8) * 2;
                uint32_t vbh[2];
                ldsm_x2t(vbh, base + 9216 + voff);
                mma16816(O[nd], aPh[kt], vbh);
            }
        }
        __syncthreads();
    }

    // ---- epilogue: hi/lo attention output ----
    const float inv0 = 1.0f / l0, inv1 = 1.0f / l1;
    const int b = bh >> 4, h = bh & 15;
    const int row0 = q0 + warp * 16 + (lane >> 2);
    const int row1 = row0 + 8;
#pragma unroll
    for (int nd = 0; nd < 8; nd++) {
        const int d = nd * 8 + (lane & 3) * 2;
        const size_t a0 = ((size_t)(b * NN + row0)) * CC + h * DD + d;
        const size_t a1 = ((size_t)(b * NN + row1)) * CC + h * DD + d;
        __half2 hh, ll;
        split2(O[nd][0] * inv0, O[nd][1] * inv0, hh, ll);
        *(__half2*)&g_aoh[a0] = hh;
        *(__half2*)&g_aol[a0] = ll;
        split2(O[nd][2] * inv1, O[nd][3] * inv1, hh, ll);
        *(__half2*)&g_aoh[a1] = hh;
        *(__half2*)&g_aol[a1] = ll;
    }
}

// ---------------------------------------------------------------------------
extern "C" void kernel_launch(void* const* d_in, const int* in_sizes, int n_in,
                              void* d_out, int out_size)
{
    const float* x     = (const float*)d_in[0];
    const float* W_qkv = (const float*)d_in[1];
    const float* W_out = (const float*)d_in[2];
    const float* b_out = (const float*)d_in[3];
    float* out = (float*)d_out;
    (void)in_sizes; (void)n_in; (void)out_size;

    cudaFuncSetAttribute(tc_gemm<0>, cudaFuncAttributeMaxDynamicSharedMemorySize, GSMEM);
    cudaFuncSetAttribute(tc_gemm<1>, cudaFuncAttributeMaxDynamicSharedMemorySize, GSMEM);
    cudaFuncSetAttribute(attn_mma_kernel, cudaFuncAttributeMaxDynamicSharedMemorySize, ATT_SMEM);

    whalf_kernel<<<(E3 * CC / 4 + 255) / 256, 256>>>(W_qkv, 0, E3 * CC / 4);
    whalf_kernel<<<(CC * CC / 4 + 255) / 256, 256>>>(W_out, 1, CC * CC / 4);

    {
        dim3 grid(E3 / 128, MM / 128);   // (24, 32)
        tc_gemm<0><<<grid, 512, GSMEM>>>(x, nullptr, nullptr);
    }
    {
        dim3 grid(NN / 128, BH);         // (16, 32)
        attn_mma_kernel<<<grid, 256, ATT_SMEM>>>();
    }
    {
        dim3 grid(CC / 128, MM / 128);   // (8, 32)
        tc_gemm<1><<<grid, 512, GSMEM>>>(nullptr, b_out, out);
    }
}